// round 16
// baseline (speedup 1.0000x reference)
#include <cuda_runtime.h>
#include <cuda_bf16.h>
#include <cstdint>

#define H4   4096
#define Bb   16
#define TPB  256
#define NCH  8                 // chunks of 64 k-rows (block K = 512)
#define RS   3                 // TMA ring slots
#define RAW_SLOT 32768         // 64 rows x 512 B fp32
#define WT_BASE  98304         // transposed bf16 weight tiles
#define WT_BUF   36864         // hi+lo per double-buffer
#define WT_SPLIT 18432
#define WT_PITCH 72            // bf16 per col-row (64 + 8 pad: conflict-free)
#define ACT_BASE 172032
#define ACT_SPLIT 16640        // 16 x 520 x 2B
#define ACT_PITCH 520          // bf16 (512 + 8 pad)
#define MB_BASE  205312
#define SMEM_NEED 205440

// scratch: 4 planes [mat*2+kc][16 b][4096] pre-activation partials (1 MB)
__device__ float g_part[4 * Bb * H4];

__device__ __forceinline__ uint32_t smem_u32(const void* p) {
    uint32_t a;
    asm("{ .reg .u64 t; cvta.to.shared.u64 t, %1; cvt.u32.u64 %0, t; }"
        : "=r"(a) : "l"(p));
    return a;
}
__device__ __forceinline__ void mbar_init(uint32_t m, uint32_t c) {
    asm volatile("mbarrier.init.shared.b64 [%0], %1;" :: "r"(m), "r"(c) : "memory");
}
__device__ __forceinline__ void mbar_expect_tx(uint32_t m, uint32_t b) {
    asm volatile("mbarrier.arrive.expect_tx.shared.b64 _, [%0], %1;"
                 :: "r"(m), "r"(b) : "memory");
}
__device__ __forceinline__ void mbar_wait(uint32_t m, uint32_t ph) {
    asm volatile(
        "{\n\t.reg .pred P;\n\t"
        "W_%=:\n\t"
        "mbarrier.try_wait.parity.acquire.cta.shared::cta.b64 P, [%0], %1, 0x989680;\n\t"
        "@P bra D_%=;\n\t"
        "bra W_%=;\n\t"
        "D_%=:\n\t}"
        :: "r"(m), "r"(ph) : "memory");
}
__device__ __forceinline__ void bulk_copy(uint32_t dst, const void* src,
                                          uint32_t bytes, uint32_t m) {
    asm volatile(
        "cp.async.bulk.shared::cluster.global.mbarrier::complete_tx::bytes "
        "[%0], [%1], %2, [%3];"
        :: "r"(dst), "l"(src), "r"(bytes), "r"(m) : "memory");
}
// warp-level bf16 MMA: D(16x8,f32) += A(16x16,row) * B(16x8,col)
__device__ __forceinline__ void mma_bf16(float* d, const uint32_t* a,
                                         uint32_t b0, uint32_t b1) {
    asm volatile(
        "mma.sync.aligned.m16n8k16.row.col.f32.bf16.bf16.f32 "
        "{%0,%1,%2,%3}, {%4,%5,%6,%7}, {%8,%9}, {%0,%1,%2,%3};"
        : "+f"(d[0]), "+f"(d[1]), "+f"(d[2]), "+f"(d[3])
        : "r"(a[0]), "r"(a[1]), "r"(a[2]), "r"(a[3]), "r"(b0), "r"(b1));
}
__device__ __forceinline__ uint32_t bfpair(float a, float b) {
    __nv_bfloat162 t;
    t.x = __float2bfloat16_rn(a);
    t.y = __float2bfloat16_rn(b);
    return *reinterpret_cast<uint32_t*>(&t);
}

// ---------------------------------------------------------------------------
// Kernel 1: split-bf16 tensor-core GEMM partials.
// grid = (32 j-tiles, 2 k-chunks, 2 matrices) = 128 blocks, 256 threads.
// Block: 128 cols x 512 k.  TMA ring (3 x 32KB) streams raw fp32 weights;
// 256 threads convert to transposed bf16 hi/lo tiles; 8 warps each run
// 2 x m16n8k16 col-tiles x 3 split-MMAs per k16-step (m = the 16 batches).
// ---------------------------------------------------------------------------
__global__ __launch_bounds__(TPB, 1) void gemm_tc(
    const float* __restrict__ Wi, const float* __restrict__ Wh,
    const float* __restrict__ x,  const float* __restrict__ h)
{
    extern __shared__ char sm[];
    const uint32_t base = smem_u32(sm);

    const int jt  = blockIdx.x;             // 0..31
    const int kc  = blockIdx.y;             // 0..1
    const int mat = blockIdx.z;             // 0: Wi/x, 1: Wh/h
    const float* __restrict__ W   = mat ? Wh : Wi;
    const float* __restrict__ act = mat ? h  : x;
    const int j0  = jt * 128;
    const int k0  = kc * 512;
    const int tid = threadIdx.x;
    const int w   = tid >> 5;
    const int lane = tid & 31;
    const int grp = lane >> 2;              // 0..7
    const int tig = lane & 3;               // 0..3

    const uint32_t mb[RS] = { base + MB_BASE, base + MB_BASE + 8, base + MB_BASE + 16 };

    if (tid == 0) {
        mbar_init(mb[0], 1); mbar_init(mb[1], 1); mbar_init(mb[2], 1);
        mbar_expect_tx(mb[0], RAW_SLOT);
        mbar_expect_tx(mb[1], RAW_SLOT);
        mbar_expect_tx(mb[2], RAW_SLOT);
    }
    __syncthreads();

    // prologue: issue TMA for chunks 0..2 (64 rows x 512 B each), spread issue
    if (tid < 192) {
        int c = tid >> 6, r = tid & 63;
        bulk_copy(base + c * RAW_SLOT + r * 512,
                  W + (size_t)(k0 + c * 64 + r) * H4 + j0, 512, mb[c]);
    }

    // convert activations -> act_hi/act_lo [b][k], bf16, pitch 520
    {
        char* ah = sm + ACT_BASE;
        char* al = ah + ACT_SPLIT;
#pragma unroll
        for (int i = 0; i < 16; i++) {
            int id = i * TPB + tid;         // 0..4095 float2-pairs
            int b  = id >> 8;
            int kp = id & 255;              // k = 2*kp
            float2 v = *reinterpret_cast<const float2*>(act + b * 1024 + k0 + 2 * kp);
            float h0 = __bfloat162float(__float2bfloat16_rn(v.x));
            float h1 = __bfloat162float(__float2bfloat16_rn(v.y));
            uint32_t off = (uint32_t)(b * ACT_PITCH + 2 * kp) * 2;
            *reinterpret_cast<uint32_t*>(ah + off) = bfpair(v.x, v.y);
            *reinterpret_cast<uint32_t*>(al + off) = bfpair(v.x - h0, v.y - h1);
        }
    }

    float d0[4] = {0.f, 0.f, 0.f, 0.f};     // col tile 0 accumulators
    float d1[4] = {0.f, 0.f, 0.f, 0.f};     // col tile 1

    const int col  = tid >> 1;              // conversion: 0..127
    const int half = tid & 1;               // k half 0..31 / 32..63

#pragma unroll
    for (int c = 0; c < NCH; c++) {
        const int slot = c % RS;
        const int p    = c & 1;
        mbar_wait(mb[slot], (c / RS) & 1);

        // convert + transpose raw fp32 chunk -> Wt_hi/Wt_lo [col][k]
        {
            char* raw = sm + slot * RAW_SLOT;
            char* wh_ = sm + WT_BASE + p * WT_BUF;
            char* wl_ = wh_ + WT_SPLIT;
#pragma unroll
            for (int i = 0; i < 16; i++) {
                int k = half * 32 + i * 2;
                float v0 = *reinterpret_cast<float*>(raw + k * 512 + col * 4);
                float v1 = *reinterpret_cast<float*>(raw + (k + 1) * 512 + col * 4);
                float h0 = __bfloat162float(__float2bfloat16_rn(v0));
                float h1 = __bfloat162float(__float2bfloat16_rn(v1));
                uint32_t off = (uint32_t)(col * WT_PITCH + k) * 2;
                *reinterpret_cast<uint32_t*>(wh_ + off) = bfpair(v0, v1);
                *reinterpret_cast<uint32_t*>(wl_ + off) = bfpair(v0 - h0, v1 - h1);
            }
        }
        if (tid == 0 && c + RS < NCH) mbar_expect_tx(mb[slot], RAW_SLOT);
        __syncthreads();
        if (c + RS < NCH && tid < 64)
            bulk_copy(base + slot * RAW_SLOT + tid * 512,
                      W + (size_t)(k0 + (c + RS) * 64 + tid) * H4 + j0, 512, mb[slot]);

        // compute: 4 k16-steps from Wt[p] + act
        {
            const char* wh_ = sm + WT_BASE + p * WT_BUF;
            const char* wl_ = wh_ + WT_SPLIT;
            const char* ah  = sm + ACT_BASE;
            const char* al  = ah + ACT_SPLIT;
#pragma unroll
            for (int ks = 0; ks < 4; ks++) {
                const int ka = c * 64 + ks * 16 + tig * 2;   // act k index
                uint32_t a_hi[4], a_lo[4];
                a_hi[0] = *reinterpret_cast<const uint32_t*>(ah + (grp * ACT_PITCH + ka) * 2);
                a_hi[1] = *reinterpret_cast<const uint32_t*>(ah + ((grp + 8) * ACT_PITCH + ka) * 2);
                a_hi[2] = *reinterpret_cast<const uint32_t*>(ah + (grp * ACT_PITCH + ka + 8) * 2);
                a_hi[3] = *reinterpret_cast<const uint32_t*>(ah + ((grp + 8) * ACT_PITCH + ka + 8) * 2);
                a_lo[0] = *reinterpret_cast<const uint32_t*>(al + (grp * ACT_PITCH + ka) * 2);
                a_lo[1] = *reinterpret_cast<const uint32_t*>(al + ((grp + 8) * ACT_PITCH + ka) * 2);
                a_lo[2] = *reinterpret_cast<const uint32_t*>(al + (grp * ACT_PITCH + ka + 8) * 2);
                a_lo[3] = *reinterpret_cast<const uint32_t*>(al + ((grp + 8) * ACT_PITCH + ka + 8) * 2);

                const int kw = ks * 16 + tig * 2;            // Wt k index
                {   // tile 0: cols w*16 + 0..7
                    int cr = w * 16 + grp;
                    uint32_t bh0 = *reinterpret_cast<const uint32_t*>(wh_ + (cr * WT_PITCH + kw) * 2);
                    uint32_t bh1 = *reinterpret_cast<const uint32_t*>(wh_ + (cr * WT_PITCH + kw + 8) * 2);
                    uint32_t bl0 = *reinterpret_cast<const uint32_t*>(wl_ + (cr * WT_PITCH + kw) * 2);
                    uint32_t bl1 = *reinterpret_cast<const uint32_t*>(wl_ + (cr * WT_PITCH + kw + 8) * 2);
                    mma_bf16(d0, a_hi, bh0, bh1);
                    mma_bf16(d0, a_hi, bl0, bl1);
                    mma_bf16(d0, a_lo, bh0, bh1);
                }
                {   // tile 1: cols w*16 + 8..15
                    int cr = w * 16 + 8 + grp;
                    uint32_t bh0 = *reinterpret_cast<const uint32_t*>(wh_ + (cr * WT_PITCH + kw) * 2);
                    uint32_t bh1 = *reinterpret_cast<const uint32_t*>(wh_ + (cr * WT_PITCH + kw + 8) * 2);
                    uint32_t bl0 = *reinterpret_cast<const uint32_t*>(wl_ + (cr * WT_PITCH + kw) * 2);
                    uint32_t bl1 = *reinterpret_cast<const uint32_t*>(wl_ + (cr * WT_PITCH + kw + 8) * 2);
                    mma_bf16(d1, a_hi, bh0, bh1);
                    mma_bf16(d1, a_hi, bl0, bl1);
                    mma_bf16(d1, a_lo, bh0, bh1);
                }
            }
        }
    }

    // epilogue: D rows = batches grp/grp+8, cols = tig*2 (+1) within 8-col tile
    {
        float* gp = g_part + (size_t)(mat * 2 + kc) * Bb * H4;
        int c0 = j0 + w * 16 + tig * 2;
        *reinterpret_cast<float2*>(gp + (size_t)grp * H4 + c0) = make_float2(d0[0], d0[1]);
        *reinterpret_cast<float2*>(gp + (size_t)(grp + 8) * H4 + c0) = make_float2(d0[2], d0[3]);
        *reinterpret_cast<float2*>(gp + (size_t)grp * H4 + c0 + 8) = make_float2(d1[0], d1[1]);
        *reinterpret_cast<float2*>(gp + (size_t)(grp + 8) * H4 + c0 + 8) = make_float2(d1[2], d1[3]);
    }
}

// ---------------------------------------------------------------------------
// Kernel 2: reduce 4 partials + biases + LSTM gates.  out = [h_new | c_new]
// ---------------------------------------------------------------------------
__global__ __launch_bounds__(256) void reduce_gates(
    const float* __restrict__ Wib, const float* __restrict__ Whb,
    const float* __restrict__ c,   float* __restrict__ out)
{
    int id = blockIdx.x * 256 + threadIdx.x;   // 0..16383
    int b = id >> 10, n = id & 1023;
    float pre[4];
#pragma unroll
    for (int g = 0; g < 4; g++) {
        int j = g * 1024 + n;
        float s = Wib[j] + Whb[j];
#pragma unroll
        for (int mp = 0; mp < 4; mp++)
            s += g_part[((size_t)(mp * Bb + b)) * H4 + j];
        pre[g] = s;
    }
    float ig = 1.0f / (1.0f + expf(-pre[0]));
    float fg = 1.0f / (1.0f + expf(-pre[1]));
    float gg = tanhf(pre[2]);
    float og = 1.0f / (1.0f + expf(-pre[3]));
    float cn = fg * c[id] + ig * gg;
    out[id] = og * tanhf(cn);
    out[Bb * 1024 + id] = cn;
}

// ---------------------------------------------------------------------------
// Inputs (metadata order): x, h, c, context, Wi, Wi_b, Wh, Wh_b, AZ_il, AZ_ir,
// AZ_hl, AZ_hr.  context / AZ_* are dead (multiplied by 0 in the reference).
// ---------------------------------------------------------------------------
extern "C" void kernel_launch(void* const* d_in, const int* in_sizes, int n_in,
                              void* d_out, int out_size)
{
    (void)in_sizes; (void)n_in; (void)out_size;
    const float* x   = (const float*)d_in[0];
    const float* h   = (const float*)d_in[1];
    const float* c   = (const float*)d_in[2];
    const float* Wi  = (const float*)d_in[4];
    const float* Wib = (const float*)d_in[5];
    const float* Wh  = (const float*)d_in[6];
    const float* Whb = (const float*)d_in[7];
    float* out = (float*)d_out;

    cudaFuncSetAttribute(gemm_tc,
                         cudaFuncAttributeMaxDynamicSharedMemorySize, SMEM_NEED);

    dim3 g(32, 2, 2);
    gemm_tc<<<g, TPB, SMEM_NEED>>>(Wi, Wh, x, h);
    reduce_gates<<<64, 256>>>(Wib, Whb, c, out);
}